// round 2
// baseline (speedup 1.0000x reference)
#include <cuda_runtime.h>
#include <stdint.h>

#define IN_F   1024
#define OUT_F  512
#define BATCH  256

// Scratch (static __device__ allocations only — no cudaMalloc allowed)
// Transposed mask: d_maskT[word][o], word = i>>5, bit (i&31) == 1 means EDGE.
__device__ uint32_t d_maskT[(IN_F / 32) * OUT_F];
// Per-batch-row bucket-grouped elements: packed (float_bits<<32 | bucket<<10 | idx)
__device__ unsigned long long d_sorted[BATCH * IN_F];

// ---------------------------------------------------------------------------
// Kernel A: compute edge mask from edge_type_count + gumbel(uniform_noise).
// idx = argmax(etc + gumbel) over last dim; no_edge = (idx==1).
// Fast path: etc0==etc1  ->  no_edge iff u1 > u0 (gumbel is strictly monotone in u).
// ---------------------------------------------------------------------------
__global__ void mask_kernel(const float* __restrict__ etc,
                            const float* __restrict__ un) {
    int t = blockIdx.x * blockDim.x + threadIdx.x;   // one thread per (o,i) pair
    int o = t >> 10;
    int i = t & (IN_F - 1);

    float2 e = reinterpret_cast<const float2*>(etc)[t];
    float2 u = reinterpret_cast<const float2*>(un)[t];

    bool no_edge;
    if (e.x == e.y) {
        no_edge = (u.y > u.x);
    } else {
        const float eps = 1e-10f;
        float g0 = -logf(-logf(u.x + eps) + eps);
        float g1 = -logf(-logf(u.y + eps) + eps);
        no_edge = (e.y + g1) > (e.x + g0);
    }

    uint32_t m = __ballot_sync(0xffffffffu, !no_edge);  // bit set == edge
    if ((threadIdx.x & 31) == 0) {
        d_maskT[(i >> 5) * OUT_F + o] = m;              // transposed layout
    }
}

// ---------------------------------------------------------------------------
// Kernel B: per batch row, counting sort of x[b][:] into 1024 value buckets.
// bucket = min(1023, (int)(v * 1024.f)) is monotone non-decreasing in v.
// Output: d_sorted[b][k] grouped by ascending bucket (within-bucket arbitrary).
// ---------------------------------------------------------------------------
__global__ void sort_kernel(const float* __restrict__ x) {
    __shared__ uint32_t hist[IN_F];
    __shared__ uint32_t wsum[8];

    int b = blockIdx.x;
    int t = threadIdx.x;          // 256 threads, 4 elements each

    for (int k = t; k < IN_F; k += 256) hist[k] = 0;
    __syncthreads();

    float4 v4 = reinterpret_cast<const float4*>(x + b * IN_F)[t];
    float vals[4] = {v4.x, v4.y, v4.z, v4.w};
    int   bkt[4];
#pragma unroll
    for (int q = 0; q < 4; q++) {
        int bb = (int)(vals[q] * 1024.0f);
        bb = bb > 1023 ? 1023 : (bb < 0 ? 0 : bb);
        bkt[q] = bb;
        atomicAdd(&hist[bb], 1u);
    }
    __syncthreads();

    // exclusive scan of 1024 counters (4 per thread + warp scan + block fixup)
    uint32_t h0 = hist[t * 4 + 0], h1 = hist[t * 4 + 1];
    uint32_t h2 = hist[t * 4 + 2], h3 = hist[t * 4 + 3];
    uint32_t s = h0 + h1 + h2 + h3;

    int lane = t & 31, w = t >> 5;
    uint32_t ss = s;
#pragma unroll
    for (int d = 1; d < 32; d <<= 1) {
        uint32_t n = __shfl_up_sync(0xffffffffu, ss, d);
        if (lane >= d) ss += n;
    }
    if (lane == 31) wsum[w] = ss;
    __syncthreads();
    if (t == 0) {
        uint32_t r = 0;
#pragma unroll
        for (int k = 0; k < 8; k++) { uint32_t v = wsum[k]; wsum[k] = r; r += v; }
    }
    __syncthreads();
    uint32_t excl = ss - s + wsum[w];
    __syncthreads();   // all reads of hist done before overwrite
    hist[t * 4 + 0] = excl;
    hist[t * 4 + 1] = excl + h0;
    hist[t * 4 + 2] = excl + h0 + h1;
    hist[t * 4 + 3] = excl + h0 + h1 + h2;
    __syncthreads();

    // scatter
#pragma unroll
    for (int q = 0; q < 4; q++) {
        int i = t * 4 + q;
        uint32_t pos = atomicAdd(&hist[bkt[q]], 1u);
        unsigned long long key =
            ((unsigned long long)__float_as_uint(vals[q]) << 32) |
            ((unsigned long long)(uint32_t)bkt[q] << 10) |
            (unsigned long long)(uint32_t)i;
        d_sorted[b * IN_F + pos] = key;
    }
}

// ---------------------------------------------------------------------------
// Kernel C: per (b,o), walk the bucket-sorted order until the first edge hit;
// then finish scanning that bucket taking exact fp32 min/max over hits.
// Even o -> min (identity/offset 2.0), odd o -> max (identity/offset -1.0).
// Warps are split so every warp walks a single direction (no divergence).
// ---------------------------------------------------------------------------
__global__ void reduce_kernel(float* __restrict__ out) {
    int b = blockIdx.x;
    int t = threadIdx.x;          // 512 threads
    int w = t >> 5, l = t & 31;

    int  o;
    bool is_min;
    if (w < 8) { o = (w * 32 + l) * 2;       is_min = true;  }
    else       { o = ((w - 8) * 32 + l) * 2 + 1; is_min = false; }

    const unsigned long long* srt = d_sorted + b * IN_F;

    float acc;
    if (is_min) {
        acc = 2.0f;            // NO_EDGE_OFFSET_T_NORM (all-no-edge fallback)
        bool found = false; int fb = -1;
        for (int k = 0; k < IN_F; k++) {
            unsigned long long e = srt[k];
            int bkt = (int)((e >> 10) & 1023u);
            if (found && bkt != fb) break;
            int idx = (int)(e & 1023u);
            uint32_t wd = d_maskT[(idx >> 5) * OUT_F + o];
            if ((wd >> (idx & 31)) & 1u) {
                float v = __uint_as_float((uint32_t)(e >> 32));
                if (!found) { found = true; fb = bkt; acc = v; }
                else        { acc = fminf(acc, v); }
            }
        }
    } else {
        acc = -1.0f;           // NO_EDGE_OFFSET_T_CONORM
        bool found = false; int fb = -1;
        for (int k = IN_F - 1; k >= 0; k--) {
            unsigned long long e = srt[k];
            int bkt = (int)((e >> 10) & 1023u);
            if (found && bkt != fb) break;
            int idx = (int)(e & 1023u);
            uint32_t wd = d_maskT[(idx >> 5) * OUT_F + o];
            if ((wd >> (idx & 31)) & 1u) {
                float v = __uint_as_float((uint32_t)(e >> 32));
                if (!found) { found = true; fb = bkt; acc = v; }
                else        { acc = fmaxf(acc, v); }
            }
        }
    }
    out[b * OUT_F + o] = acc;
}

// ---------------------------------------------------------------------------
extern "C" void kernel_launch(void* const* d_in, const int* in_sizes, int n_in,
                              void* d_out, int out_size) {
    const float* x    = (const float*)d_in[0];   // [256,1024]
    const float* etc  = (const float*)d_in[1];   // [512,1024,2]
    const float* un   = (const float*)d_in[2];   // [512,1024,2]
    float* out = (float*)d_out;                  // [256,512]

    mask_kernel<<<(OUT_F * IN_F) / 256, 256>>>(etc, un);
    sort_kernel<<<BATCH, 256>>>(x);
    reduce_kernel<<<BATCH, 512>>>(out);
}

// round 3
// speedup vs baseline: 1.1299x; 1.1299x over previous
#include <cuda_runtime.h>
#include <stdint.h>

#define IN_F   1024
#define OUT_F  512
#define BATCH  256

// Scratch (static __device__ allocations only)
// Transposed mask: d_maskT[word][o], word = i>>5; bit (i&31)==1 means EDGE.
__device__ uint32_t d_maskT[(IN_F / 32) * OUT_F];
// Per-batch-row bucket-grouped elements: packed (float_bits<<32 | bucket<<10 | idx)
__device__ unsigned long long d_sorted[BATCH * IN_F];

#define SORT_BLOCKS  BATCH            // 256
#define MASK_BLOCKS  512              // 512*256 threads * 4 pairs = 512K pairs
#define THREADS      256

// ---------------------------------------------------------------------------
// Fused kernel: blocks [0,256) do the per-row counting sort of x;
// blocks [256,768) compute the edge mask. The two tasks are independent and
// now overlap on the SMs instead of serializing across launches.
// ---------------------------------------------------------------------------
__global__ void prep_kernel(const float* __restrict__ x,
                            const float* __restrict__ etc,
                            const float* __restrict__ un) {
    __shared__ uint32_t hist[IN_F];
    __shared__ uint32_t wsum[8];

    int t = threadIdx.x;

    if (blockIdx.x >= SORT_BLOCKS) {
        // ---------------- MASK part: 4 pairs per thread, lane-strided -------
        // warp_g covers 128 consecutive (o,i) pairs; lane l handles
        // base+l, base+32+l, base+64+l, base+96+l  ->  each ballot is one
        // contiguous 32-bit mask word. 8 independent 8B loads per thread.
        int mb = blockIdx.x - SORT_BLOCKS;
        int warp_g = (mb * THREADS + t) >> 5;
        int lane   = t & 31;
        int base   = warp_g * 128;

        float2 e[4], u[4];
#pragma unroll
        for (int g = 0; g < 4; g++) {
            int p = base + g * 32 + lane;
            e[g] = reinterpret_cast<const float2*>(etc)[p];
            u[g] = reinterpret_cast<const float2*>(un)[p];
        }
#pragma unroll
        for (int g = 0; g < 4; g++) {
            int p = base + g * 32 + lane;
            bool no_edge;
            if (e[g].x == e[g].y) {
                no_edge = (u[g].y > u[g].x);   // gumbel monotone in uniform
            } else {
                const float eps = 1e-10f;
                float g0 = -logf(-logf(u[g].x + eps) + eps);
                float g1 = -logf(-logf(u[g].y + eps) + eps);
                no_edge = (e[g].y + g1) > (e[g].x + g0);
            }
            uint32_t m = __ballot_sync(0xffffffffu, !no_edge);
            if (lane == 0) {
                int i = p & (IN_F - 1);
                int o = p >> 10;
                d_maskT[(i >> 5) * OUT_F + o] = m;
            }
        }
        return;
    }

    // ---------------- SORT part: counting sort of one batch row ------------
    int b = blockIdx.x;

    for (int k = t; k < IN_F; k += THREADS) hist[k] = 0;
    __syncthreads();

    float4 v4 = reinterpret_cast<const float4*>(x + b * IN_F)[t];
    float vals[4] = {v4.x, v4.y, v4.z, v4.w};
    int   bkt[4];
#pragma unroll
    for (int q = 0; q < 4; q++) {
        int bb = (int)(vals[q] * 1024.0f);
        bb = bb > 1023 ? 1023 : (bb < 0 ? 0 : bb);
        bkt[q] = bb;
        atomicAdd(&hist[bb], 1u);
    }
    __syncthreads();

    // exclusive scan of 1024 counters
    uint32_t h0 = hist[t * 4 + 0], h1 = hist[t * 4 + 1];
    uint32_t h2 = hist[t * 4 + 2], h3 = hist[t * 4 + 3];
    uint32_t s = h0 + h1 + h2 + h3;

    int lane = t & 31, w = t >> 5;
    uint32_t ss = s;
#pragma unroll
    for (int d = 1; d < 32; d <<= 1) {
        uint32_t n = __shfl_up_sync(0xffffffffu, ss, d);
        if (lane >= d) ss += n;
    }
    if (lane == 31) wsum[w] = ss;
    __syncthreads();
    if (t == 0) {
        uint32_t r = 0;
#pragma unroll
        for (int k = 0; k < 8; k++) { uint32_t v = wsum[k]; wsum[k] = r; r += v; }
    }
    __syncthreads();
    uint32_t excl = ss - s + wsum[w];
    __syncthreads();
    hist[t * 4 + 0] = excl;
    hist[t * 4 + 1] = excl + h0;
    hist[t * 4 + 2] = excl + h0 + h1;
    hist[t * 4 + 3] = excl + h0 + h1 + h2;
    __syncthreads();

#pragma unroll
    for (int q = 0; q < 4; q++) {
        int i = t * 4 + q;
        uint32_t pos = atomicAdd(&hist[bkt[q]], 1u);
        unsigned long long key =
            ((unsigned long long)__float_as_uint(vals[q]) << 32) |
            ((unsigned long long)(uint32_t)bkt[q] << 10) |
            (unsigned long long)(uint32_t)i;
        d_sorted[b * IN_F + pos] = key;
    }
}

// ---------------------------------------------------------------------------
// Kernel C: per (b,o), walk the bucket-sorted order until the first edge hit;
// finish scanning that bucket taking exact fp32 min/max over hits.
// ---------------------------------------------------------------------------
__global__ void reduce_kernel(float* __restrict__ out) {
    int b = blockIdx.x;
    int t = threadIdx.x;          // 512 threads
    int w = t >> 5, l = t & 31;

    int  o;
    bool is_min;
    if (w < 8) { o = (w * 32 + l) * 2;           is_min = true;  }
    else       { o = ((w - 8) * 32 + l) * 2 + 1; is_min = false; }

    const unsigned long long* srt = d_sorted + b * IN_F;

    float acc;
    if (is_min) {
        acc = 2.0f;            // NO_EDGE_OFFSET_T_NORM fallback
        bool found = false; int fb = -1;
        for (int k = 0; k < IN_F; k++) {
            unsigned long long e = srt[k];
            int bkt = (int)((e >> 10) & 1023u);
            if (found && bkt != fb) break;
            int idx = (int)(e & 1023u);
            uint32_t wd = d_maskT[(idx >> 5) * OUT_F + o];
            if ((wd >> (idx & 31)) & 1u) {
                float v = __uint_as_float((uint32_t)(e >> 32));
                if (!found) { found = true; fb = bkt; acc = v; }
                else        { acc = fminf(acc, v); }
            }
        }
    } else {
        acc = -1.0f;           // NO_EDGE_OFFSET_T_CONORM fallback
        bool found = false; int fb = -1;
        for (int k = IN_F - 1; k >= 0; k--) {
            unsigned long long e = srt[k];
            int bkt = (int)((e >> 10) & 1023u);
            if (found && bkt != fb) break;
            int idx = (int)(e & 1023u);
            uint32_t wd = d_maskT[(idx >> 5) * OUT_F + o];
            if ((wd >> (idx & 31)) & 1u) {
                float v = __uint_as_float((uint32_t)(e >> 32));
                if (!found) { found = true; fb = bkt; acc = v; }
                else        { acc = fmaxf(acc, v); }
            }
        }
    }
    out[b * OUT_F + o] = acc;
}

// ---------------------------------------------------------------------------
extern "C" void kernel_launch(void* const* d_in, const int* in_sizes, int n_in,
                              void* d_out, int out_size) {
    const float* x    = (const float*)d_in[0];   // [256,1024]
    const float* etc  = (const float*)d_in[1];   // [512,1024,2]
    const float* un   = (const float*)d_in[2];   // [512,1024,2]
    float* out = (float*)d_out;                  // [256,512]

    prep_kernel<<<SORT_BLOCKS + MASK_BLOCKS, THREADS>>>(x, etc, un);
    reduce_kernel<<<BATCH, 512>>>(out);
}

// round 4
// speedup vs baseline: 1.1525x; 1.0200x over previous
#include <cuda_runtime.h>
#include <stdint.h>

#define IN_F   1024
#define OUT_F  512
#define BATCH  256

typedef unsigned long long ull;

// Transposed mask: d_maskT[word][o], word = i>>5; bit (i&31)==1 means EDGE.
__device__ uint32_t d_maskT[(IN_F / 32) * OUT_F];
// Per-batch-row bucket-grouped elements: packed (float_bits<<32 | bucket<<10 | idx)
__device__ ull d_sorted[BATCH * IN_F];

#define SORT_BLOCKS  BATCH            // 256
#define MASK_BLOCKS  256              // 256 blk * 8 warps * 8 groups * 32 = 512K pairs
#define THREADS      256

// ---------------------------------------------------------------------------
// Fused prep: blocks [0,256) counting-sort one x row each;
// blocks [256,512) compute the edge mask, 8 pairs/thread (16 loads in flight).
// ---------------------------------------------------------------------------
__global__ void prep_kernel(const float* __restrict__ x,
                            const float* __restrict__ etc,
                            const float* __restrict__ un) {
    __shared__ uint32_t hist[IN_F];
    __shared__ uint32_t wsum[8];

    int t = threadIdx.x;

    if (blockIdx.x >= SORT_BLOCKS) {
        // ---------------- MASK: 8 lane-strided pairs per thread ------------
        int mb     = blockIdx.x - SORT_BLOCKS;
        int warp_g = (mb * THREADS + t) >> 5;   // 2048 warps total
        int lane   = t & 31;
        int base   = warp_g * 256;              // 256 pairs per warp

        float2 e[8], u[8];
#pragma unroll
        for (int g = 0; g < 8; g++) {
            int p = base + g * 32 + lane;
            e[g] = reinterpret_cast<const float2*>(etc)[p];
            u[g] = reinterpret_cast<const float2*>(un)[p];
        }
#pragma unroll
        for (int g = 0; g < 8; g++) {
            int p = base + g * 32 + lane;
            bool no_edge;
            if (e[g].x == e[g].y) {
                no_edge = (u[g].y > u[g].x);    // gumbel monotone in uniform
            } else {
                const float eps = 1e-10f;
                float g0 = -logf(-logf(u[g].x + eps) + eps);
                float g1 = -logf(-logf(u[g].y + eps) + eps);
                no_edge = (e[g].y + g1) > (e[g].x + g0);
            }
            uint32_t m = __ballot_sync(0xffffffffu, !no_edge);
            if (lane == 0) {
                int i = p & (IN_F - 1);
                int o = p >> 10;
                d_maskT[(i >> 5) * OUT_F + o] = m;
            }
        }
        return;
    }

    // ---------------- SORT: counting sort of one batch row -----------------
    int b = blockIdx.x;

    for (int k = t; k < IN_F; k += THREADS) hist[k] = 0;
    __syncthreads();

    float4 v4 = reinterpret_cast<const float4*>(x + b * IN_F)[t];
    float vals[4] = {v4.x, v4.y, v4.z, v4.w};
    int   bkt[4];
#pragma unroll
    for (int q = 0; q < 4; q++) {
        int bb = (int)(vals[q] * 1024.0f);
        bb = bb > 1023 ? 1023 : (bb < 0 ? 0 : bb);
        bkt[q] = bb;
        atomicAdd(&hist[bb], 1u);
    }
    __syncthreads();

    uint32_t h0 = hist[t * 4 + 0], h1 = hist[t * 4 + 1];
    uint32_t h2 = hist[t * 4 + 2], h3 = hist[t * 4 + 3];
    uint32_t s = h0 + h1 + h2 + h3;

    int lane = t & 31, w = t >> 5;
    uint32_t ss = s;
#pragma unroll
    for (int d = 1; d < 32; d <<= 1) {
        uint32_t n = __shfl_up_sync(0xffffffffu, ss, d);
        if (lane >= d) ss += n;
    }
    if (lane == 31) wsum[w] = ss;
    __syncthreads();
    if (t == 0) {
        uint32_t r = 0;
#pragma unroll
        for (int k = 0; k < 8; k++) { uint32_t v = wsum[k]; wsum[k] = r; r += v; }
    }
    __syncthreads();
    uint32_t excl = ss - s + wsum[w];
    __syncthreads();
    hist[t * 4 + 0] = excl;
    hist[t * 4 + 1] = excl + h0;
    hist[t * 4 + 2] = excl + h0 + h1;
    hist[t * 4 + 3] = excl + h0 + h1 + h2;
    __syncthreads();

#pragma unroll
    for (int q = 0; q < 4; q++) {
        int i = t * 4 + q;
        uint32_t pos = atomicAdd(&hist[bkt[q]], 1u);
        ull key = ((ull)__float_as_uint(vals[q]) << 32) |
                  ((ull)(uint32_t)bkt[q] << 10) |
                  (ull)(uint32_t)i;
        d_sorted[b * IN_F + pos] = key;
    }
}

// ---------------------------------------------------------------------------
// Reduce v2: 512 blocks x 256 threads. blk = (b, half); half 0 = min over
// even o (ascending walk), half 1 = max over odd o (descending walk).
// Batched probing: 8 broadcast sorted-entry loads (round 1), then 8
// independent mask loads (round 2). Sequential fallback for the rare tail.
// ---------------------------------------------------------------------------
__global__ void reduce_kernel(float* __restrict__ out) {
    int blk  = blockIdx.x;
    int b    = blk >> 1;
    int half = blk & 1;                 // 0 -> min/even o, 1 -> max/odd o
    int t    = threadIdx.x;             // 256
    int o    = 2 * t + half;

    const ull* srt = d_sorted + b * IN_F;

    ull e[8];
#pragma unroll
    for (int k = 0; k < 8; k++)
        e[k] = half ? srt[IN_F - 1 - k] : srt[k];   // warp-uniform broadcast

    uint32_t m[8];
#pragma unroll
    for (int k = 0; k < 8; k++) {
        int idx = (int)(e[k] & 1023u);
        m[k] = d_maskT[(idx >> 5) * OUT_F + o];     // 8 independent loads
    }

    float acc   = half ? -1.0f : 2.0f;  // no-edge offsets
    bool  found = false, done = false;
    int   fb    = -1;

#pragma unroll
    for (int k = 0; k < 8; k++) {
        int bkt = (int)((e[k] >> 10) & 1023u);
        if (found && bkt != fb) { done = true; break; }
        int idx = (int)(e[k] & 1023u);
        if ((m[k] >> (idx & 31)) & 1u) {
            float v = __uint_as_float((uint32_t)(e[k] >> 32));
            if (!found) { found = true; fb = bkt; acc = v; }
            else        { acc = half ? fmaxf(acc, v) : fminf(acc, v); }
        }
    }

    if (!done) {                        // rare: resolve remainder sequentially
        for (int k = 8; k < IN_F; k++) {
            ull ee = half ? srt[IN_F - 1 - k] : srt[k];
            int bkt = (int)((ee >> 10) & 1023u);
            if (found && bkt != fb) break;
            int idx = (int)(ee & 1023u);
            uint32_t wd = d_maskT[(idx >> 5) * OUT_F + o];
            if ((wd >> (idx & 31)) & 1u) {
                float v = __uint_as_float((uint32_t)(ee >> 32));
                if (!found) { found = true; fb = bkt; acc = v; }
                else        { acc = half ? fmaxf(acc, v) : fminf(acc, v); }
            }
        }
    }

    out[b * OUT_F + o] = acc;
}

// ---------------------------------------------------------------------------
extern "C" void kernel_launch(void* const* d_in, const int* in_sizes, int n_in,
                              void* d_out, int out_size) {
    const float* x    = (const float*)d_in[0];   // [256,1024]
    const float* etc  = (const float*)d_in[1];   // [512,1024,2]
    const float* un   = (const float*)d_in[2];   // [512,1024,2]
    float* out = (float*)d_out;                  // [256,512]

    prep_kernel<<<SORT_BLOCKS + MASK_BLOCKS, THREADS>>>(x, etc, un);
    reduce_kernel<<<BATCH * 2, THREADS>>>(out);
}

// round 6
// speedup vs baseline: 1.2359x; 1.0724x over previous
#include <cuda_runtime.h>
#include <stdint.h>

#define IN_F   1024
#define OUT_F  512
#define BATCH  256

typedef unsigned long long ull;

// Transposed mask: d_maskT[word][o], word = i>>5; bit (i&31)==1 means EDGE.
__device__ uint32_t d_maskT[(IN_F / 32) * OUT_F];
// Per-batch-row bucket-grouped elements: packed (float_bits<<32 | bucket<<10 | idx)
__device__ ull d_sorted[BATCH * IN_F];

#define SORT_BLOCKS  BATCH            // 256
#define MASK_BLOCKS  256              // 256 blk * 8 warps * 256 pairs = 512K pairs
#define THREADS      256

// ---------------------------------------------------------------------------
// Fused prep: blocks [0,256) counting-sort one x row each;
// blocks [256,512) compute the edge mask, 8 pairs/thread (16 loads in flight).
// ---------------------------------------------------------------------------
__global__ void prep_kernel(const float* __restrict__ x,
                            const float* __restrict__ etc,
                            const float* __restrict__ un) {
    __shared__ uint32_t hist[IN_F];
    __shared__ uint32_t wsum[8];

    int t = threadIdx.x;

    if (blockIdx.x >= SORT_BLOCKS) {
        // ---------------- MASK: 8 lane-strided pairs per thread ------------
        int mb     = blockIdx.x - SORT_BLOCKS;
        int warp_g = (mb * THREADS + t) >> 5;   // 2048 warps total
        int lane   = t & 31;
        int base   = warp_g * 256;              // 256 pairs per warp

        float2 e[8], u[8];
#pragma unroll
        for (int g = 0; g < 8; g++) {
            int p = base + g * 32 + lane;
            e[g] = reinterpret_cast<const float2*>(etc)[p];
            u[g] = reinterpret_cast<const float2*>(un)[p];
        }
#pragma unroll
        for (int g = 0; g < 8; g++) {
            int p = base + g * 32 + lane;
            bool no_edge;
            if (e[g].x == e[g].y) {
                no_edge = (u[g].y > u[g].x);    // gumbel monotone in uniform
            } else {
                const float eps = 1e-10f;
                float g0 = -logf(-logf(u[g].x + eps) + eps);
                float g1 = -logf(-logf(u[g].y + eps) + eps);
                no_edge = (e[g].y + g1) > (e[g].x + g0);
            }
            uint32_t m = __ballot_sync(0xffffffffu, !no_edge);
            if (lane == 0) {
                int i = p & (IN_F - 1);
                int o = p >> 10;
                d_maskT[(i >> 5) * OUT_F + o] = m;
            }
        }
        return;
    }

    // ---------------- SORT: counting sort of one batch row -----------------
    int b = blockIdx.x;

    for (int k = t; k < IN_F; k += THREADS) hist[k] = 0;
    __syncthreads();

    float4 v4 = reinterpret_cast<const float4*>(x + b * IN_F)[t];
    float vals[4] = {v4.x, v4.y, v4.z, v4.w};
    int   bkt[4];
#pragma unroll
    for (int q = 0; q < 4; q++) {
        int bb = (int)(vals[q] * 1024.0f);
        bb = bb > 1023 ? 1023 : (bb < 0 ? 0 : bb);
        bkt[q] = bb;
        atomicAdd(&hist[bb], 1u);
    }
    __syncthreads();

    uint32_t h0 = hist[t * 4 + 0], h1 = hist[t * 4 + 1];
    uint32_t h2 = hist[t * 4 + 2], h3 = hist[t * 4 + 3];
    uint32_t s = h0 + h1 + h2 + h3;

    int lane = t & 31, w = t >> 5;
    uint32_t ss = s;
#pragma unroll
    for (int d = 1; d < 32; d <<= 1) {
        uint32_t n = __shfl_up_sync(0xffffffffu, ss, d);
        if (lane >= d) ss += n;
    }
    if (lane == 31) wsum[w] = ss;
    __syncthreads();
    if (t == 0) {
        uint32_t r = 0;
#pragma unroll
        for (int k = 0; k < 8; k++) { uint32_t v = wsum[k]; wsum[k] = r; r += v; }
    }
    __syncthreads();
    uint32_t excl = ss - s + wsum[w];
    __syncthreads();
    hist[t * 4 + 0] = excl;
    hist[t * 4 + 1] = excl + h0;
    hist[t * 4 + 2] = excl + h0 + h1;
    hist[t * 4 + 3] = excl + h0 + h1 + h2;
    __syncthreads();

#pragma unroll
    for (int q = 0; q < 4; q++) {
        int i = t * 4 + q;
        uint32_t pos = atomicAdd(&hist[bkt[q]], 1u);
        ull key = ((ull)__float_as_uint(vals[q]) << 32) |
                  ((ull)(uint32_t)bkt[q] << 10) |
                  (ull)(uint32_t)i;
        d_sorted[b * IN_F + pos] = key;
    }
}

// ---------------------------------------------------------------------------
// Reduce v4: 512 blocks x 256 threads; blk=(b,half). half 0 = min over even o
// (ascending), half 1 = max over odd o (descending).
// Round 1: each LANE loads ONE sorted entry (single coalesced LDG.64 gives
//          the warp 32 entries). ALL shuffles happen in uniform unrolled
//          loops BEFORE any divergent control flow (that was the R5 bug:
//          __shfl_sync after a data-dependent break = UB).
// Round 2: DEPTH independent mask loads, then a register-only divergent scan.
// ---------------------------------------------------------------------------
#define DEPTH 16

__global__ void reduce_kernel(float* __restrict__ out) {
    const uint32_t FULL = 0xffffffffu;
    int blk  = blockIdx.x;
    int b    = blk >> 1;
    int half = blk & 1;                 // 0 -> min/even o, 1 -> max/odd o
    int t    = threadIdx.x;             // 256
    int lane = t & 31;
    int o    = 2 * t + half;

    const ull* srt = d_sorted + b * IN_F;

    // Round 1: one coalesced entry per lane; broadcast all DEPTH (uniform).
    ull mye = half ? srt[IN_F - 1 - lane] : srt[lane];
    ull e[DEPTH];
#pragma unroll
    for (int k = 0; k < DEPTH; k++)
        e[k] = __shfl_sync(FULL, mye, k);       // no divergence here

    // Round 2: DEPTH independent mask loads (uniform loop, no branches).
    uint32_t m[DEPTH];
#pragma unroll
    for (int k = 0; k < DEPTH; k++) {
        int idxk = (int)(e[k] & 1023u);
        m[k] = d_maskT[(idxk >> 5) * OUT_F + o];
    }

    // Register-only scan; divergence is now safe (no sync ops inside).
    float acc   = half ? -1.0f : 2.0f;  // no-edge offsets
    bool  found = false, done = false;
    int   fb    = -1;

#pragma unroll
    for (int k = 0; k < DEPTH; k++) {
        int bkt = (int)((e[k] >> 10) & 1023u);
        if (found && bkt != fb) { done = true; break; }
        int idx = (int)(e[k] & 1023u);
        if ((m[k] >> (idx & 31)) & 1u) {
            float v = __uint_as_float((uint32_t)(e[k] >> 32));
            if (!found) { found = true; fb = bkt; acc = v; }
            else        { acc = half ? fmaxf(acc, v) : fminf(acc, v); }
        }
    }

    if (!done) {                        // ~2^-16 per thread: sequential tail
        for (int k = DEPTH; k < IN_F; k++) {
            ull ee = half ? srt[IN_F - 1 - k] : srt[k];
            int bkt = (int)((ee >> 10) & 1023u);
            if (found && bkt != fb) break;
            int idx = (int)(ee & 1023u);
            uint32_t wd = d_maskT[(idx >> 5) * OUT_F + o];
            if ((wd >> (idx & 31)) & 1u) {
                float v = __uint_as_float((uint32_t)(ee >> 32));
                if (!found) { found = true; fb = bkt; acc = v; }
                else        { acc = half ? fmaxf(acc, v) : fminf(acc, v); }
            }
        }
    }

    out[b * OUT_F + o] = acc;
}

// ---------------------------------------------------------------------------
extern "C" void kernel_launch(void* const* d_in, const int* in_sizes, int n_in,
                              void* d_out, int out_size) {
    const float* x    = (const float*)d_in[0];   // [256,1024]
    const float* etc  = (const float*)d_in[1];   // [512,1024,2]
    const float* un   = (const float*)d_in[2];   // [512,1024,2]
    float* out = (float*)d_out;                  // [256,512]

    prep_kernel<<<SORT_BLOCKS + MASK_BLOCKS, THREADS>>>(x, etc, un);
    reduce_kernel<<<BATCH * 2, THREADS>>>(out);
}